// round 8
// baseline (speedup 1.0000x reference)
#include <cuda_runtime.h>
#include <cuda_bf16.h>
#include <cstdint>

// Output = one_hot(arange(N), N) @ W = I @ W = W: an 8 MiB D2D copy.
//
// Converged model (R1-R7): wallclock ~6.6us = graph replay + launch +
// one idle-DVFS-clock memory round-trip + ~1.8us of actual transfer.
// Invariant to request path (LDG/TMA/CE/split), occupancy, and MLP depth.
// Best measured geometry: 512 CTAs x 256 threads x MLP4 (5.888us kernel)
// -- many moderately-deep warps beat few deep ones (shallower per-warp
// L1tex queue, faster dispatch spread). Final: that geometry + L2-only
// loads (__ldcg) + streaming stores (__stcs).

__global__ void __launch_bounds__(256) copy_w_final(const float4* __restrict__ src,
                                                    float4* __restrict__ dst) {
    // 512 CTAs x 256 threads x 4 vec4 = 524288 vec4 = 8 MiB, exact tiling.
    // Contiguous 16 KiB tile per CTA; stride-256 -> fully coalesced 128B
    // per warp access. 4 independent loads front-batched (MLP_p1 = 4).
    int base = blockIdx.x * (256 * 4) + threadIdx.x;

    float4 a0 = __ldcg(&src[base + 0 * 256]);
    float4 a1 = __ldcg(&src[base + 1 * 256]);
    float4 a2 = __ldcg(&src[base + 2 * 256]);
    float4 a3 = __ldcg(&src[base + 3 * 256]);

    __stcs(&dst[base + 0 * 256], a0);
    __stcs(&dst[base + 1 * 256], a1);
    __stcs(&dst[base + 2 * 256], a2);
    __stcs(&dst[base + 3 * 256], a3);
}

extern "C" void kernel_launch(void* const* d_in, const int* in_sizes, int n_in,
                              void* d_out, int out_size) {
    const float4* W = (const float4*)d_in[0];
    float4* out = (float4*)d_out;
    // out_size = 16384*128 = 2097152 floats = 524288 vec4 -> 512 CTAs exact.
    int blocks = out_size / (4 * 256 * 4);
    copy_w_final<<<blocks, 256>>>(W, out);
}